// round 1
// baseline (speedup 1.0000x reference)
#include <cuda_runtime.h>
#include <math.h>

#define Bn 16
#define Ln 2048
#define Mn 32000
#define Dn 512

// ---------------- scratch (no allocations allowed) ----------------
__device__ float g_inv_e[Mn + 1];          // 1/max(||emb row||,1)
__device__ float g_inv_p[Ln];              // 1/max(||pos row||,1)
__device__ float g_logits[Bn * Ln];
__device__ float g_att[Bn * Ln];
__device__ float g_partial[Bn * 16 * Dn];  // 512KB
__device__ float g_sel[Bn * Dn];
__device__ float g_ip[Bn * Mn];            // 2MB
__device__ float g_logp[Bn];

// ---------------- K1: row inverse norms (warp per row) ----------------
__global__ void k_norm(const float* __restrict__ src, int nrows, int which) {
    int warp = (blockIdx.x * blockDim.x + threadIdx.x) >> 5;
    int lane = threadIdx.x & 31;
    if (warp >= nrows) return;
    const float* r = src + (size_t)warp * Dn;
    float s = 0.f;
#pragma unroll
    for (int j = 0; j < 16; j++) { float v = r[lane + 32 * j]; s += v * v; }
#pragma unroll
    for (int o = 16; o; o >>= 1) s += __shfl_xor_sync(0xffffffffu, s, o);
    if (lane == 0) {
        float inv = 1.0f / fmaxf(sqrtf(s), 1.0f);
        if (which == 0) g_inv_e[warp] = inv; else g_inv_p[warp] = inv;
    }
}

// ---------------- K2: logits[b,m] = (q.c + p_mb.p_m)/32 ----------------
// grid (Ln/8, Bn), block 256 (8 warps, warp per m)
__global__ __launch_bounds__(256) void k_logits(
    const float* __restrict__ emb, const float* __restrict__ pos,
    const int* __restrict__ x, const int* __restrict__ mask_idx) {
    __shared__ float qs[Dn];
    __shared__ float ps[Dn];
    int b = blockIdx.y;
    int mb = mask_idx[b];
    float ie_m = g_inv_e[Mn];
    float ip_mb = g_inv_p[mb];
    for (int i = threadIdx.x; i < Dn; i += blockDim.x) {
        qs[i] = emb[(size_t)Mn * Dn + i] * ie_m;
        ps[i] = pos[(size_t)mb * Dn + i] * ip_mb;
    }
    __syncthreads();
    int wid = threadIdx.x >> 5, lane = threadIdx.x & 31;
    int m = blockIdx.x * 8 + wid;
    int tok = (m == mb) ? Mn : x[b * Ln + m];
    const float* er = emb + (size_t)tok * Dn;
    const float* pr = pos + (size_t)m * Dn;
    float dc = 0.f, dp = 0.f;
#pragma unroll
    for (int j = 0; j < 16; j++) {
        int c = lane + 32 * j;
        dc += er[c] * qs[c];
        dp += pr[c] * ps[c];
    }
    float s = dc * g_inv_e[tok] + dp * g_inv_p[m];
#pragma unroll
    for (int o = 16; o; o >>= 1) s += __shfl_xor_sync(0xffffffffu, s, o);
    if (lane == 0) g_logits[b * Ln + m] = s * (1.0f / 32.0f);
}

// ---------------- K3: softmax over m per batch (block per b) ----------------
__global__ __launch_bounds__(256) void k_softmax() {
    int b = blockIdx.x;
    __shared__ float sh[Ln];
    __shared__ float red[8];
    __shared__ float s_mx, s_sum;
    int tid = threadIdx.x;
    float mx = -1e30f;
    for (int i = tid; i < Ln; i += 256) {
        float v = g_logits[b * Ln + i];
        sh[i] = v;
        mx = fmaxf(mx, v);
    }
#pragma unroll
    for (int o = 16; o; o >>= 1) mx = fmaxf(mx, __shfl_xor_sync(0xffffffffu, mx, o));
    if ((tid & 31) == 0) red[tid >> 5] = mx;
    __syncthreads();
    if (tid == 0) {
        float v = red[0];
#pragma unroll
        for (int i = 1; i < 8; i++) v = fmaxf(v, red[i]);
        s_mx = v;
    }
    __syncthreads();
    float maxv = s_mx;
    __syncthreads();
    float sm = 0.f;
    for (int i = tid; i < Ln; i += 256) {
        float e = __expf(sh[i] - maxv);
        sh[i] = e;
        sm += e;
    }
#pragma unroll
    for (int o = 16; o; o >>= 1) sm += __shfl_xor_sync(0xffffffffu, sm, o);
    if ((tid & 31) == 0) red[tid >> 5] = sm;
    __syncthreads();
    if (tid == 0) {
        float v = 0.f;
#pragma unroll
        for (int i = 0; i < 8; i++) v += red[i];
        s_sum = v;
    }
    __syncthreads();
    float inv = 1.0f / s_sum;
    for (int i = tid; i < Ln; i += 256) g_att[b * Ln + i] = sh[i] * inv;
}

// ---------------- K4: weighted gather-sum partials ----------------
// grid (16 chunks, Bn), block 512, thread = d
__global__ __launch_bounds__(512) void k_wsum(
    const float* __restrict__ emb, const int* __restrict__ x,
    const int* __restrict__ mask_idx) {
    __shared__ float wsh[128];
    __shared__ int tsh[128];
    int b = blockIdx.y, c = blockIdx.x;
    int tid = threadIdx.x;
    int mb = mask_idx[b];
    if (tid < 128) {
        int m = c * 128 + tid;
        int tok = (m == mb) ? Mn : x[b * Ln + m];
        tsh[tid] = tok;
        wsh[tid] = g_att[b * Ln + m] * g_inv_e[tok];
    }
    __syncthreads();
    float acc = 0.f;
    int d = tid;
#pragma unroll 4
    for (int i = 0; i < 128; i++)
        acc += emb[(size_t)tsh[i] * Dn + d] * wsh[i];
    g_partial[(b * 16 + c) * Dn + d] = acc;
}

// ---------------- K5: reduce partials -> sel_output ----------------
__global__ __launch_bounds__(512) void k_reduce_sel(float* __restrict__ out_sel) {
    int b = blockIdx.x, d = threadIdx.x;
    float s = 0.f;
#pragma unroll
    for (int c = 0; c < 16; c++) s += g_partial[(b * 16 + c) * Dn + d];
    g_sel[b * Dn + d] = s;
    if (out_sel) out_sel[b * Dn + d] = s;
}

// ---------------- K6: inner_prod[b,t] = sel[b] . (emb[t]*inv_e[t]) --------
// block 128 (4 warps), warp w owns batches 4w..4w+3 with sel in registers.
// grid = Mn/32, 32 tokens per block.
__global__ __launch_bounds__(128) void k_ip(const float* __restrict__ emb) {
    int w = threadIdx.x >> 5, lane = threadIdx.x & 31;
    float selr[4][16];
#pragma unroll
    for (int bb = 0; bb < 4; bb++)
#pragma unroll
        for (int j = 0; j < 16; j++)
            selr[bb][j] = g_sel[(w * 4 + bb) * Dn + lane + 32 * j];
    int t0 = blockIdx.x * 32;
    for (int ti = 0; ti < 32; ti++) {
        int t = t0 + ti;
        const float* er = emb + (size_t)t * Dn;
        float e[16];
#pragma unroll
        for (int j = 0; j < 16; j++) e[j] = er[lane + 32 * j];
        float acc[4] = {0.f, 0.f, 0.f, 0.f};
#pragma unroll
        for (int j = 0; j < 16; j++)
#pragma unroll
            for (int bb = 0; bb < 4; bb++)
                acc[bb] += e[j] * selr[bb][j];
        float sc = g_inv_e[t];
#pragma unroll
        for (int bb = 0; bb < 4; bb++) {
            float v = acc[bb];
#pragma unroll
            for (int o = 16; o; o >>= 1) v += __shfl_xor_sync(0xffffffffu, v, o);
            if (lane == 0) g_ip[(w * 4 + bb) * Mn + t] = v * sc;
        }
    }
}

// ---------------- K7: per-batch log-softmax at target ----------------
__global__ __launch_bounds__(256) void k_lsm(const int* __restrict__ x,
                                             const int* __restrict__ mask_idx) {
    int b = blockIdx.x, tid = threadIdx.x;
    __shared__ float red[8];
    __shared__ float s_mx;
    float mx = -1e30f;
    for (int i = tid; i < Mn; i += 256) mx = fmaxf(mx, g_ip[b * Mn + i]);
#pragma unroll
    for (int o = 16; o; o >>= 1) mx = fmaxf(mx, __shfl_xor_sync(0xffffffffu, mx, o));
    if ((tid & 31) == 0) red[tid >> 5] = mx;
    __syncthreads();
    if (tid == 0) {
        float v = red[0];
#pragma unroll
        for (int i = 1; i < 8; i++) v = fmaxf(v, red[i]);
        s_mx = v;
    }
    __syncthreads();
    float maxv = s_mx;
    __syncthreads();
    float sm = 0.f;
    for (int i = tid; i < Mn; i += 256) sm += __expf(g_ip[b * Mn + i] - maxv);
#pragma unroll
    for (int o = 16; o; o >>= 1) sm += __shfl_xor_sync(0xffffffffu, sm, o);
    if ((tid & 31) == 0) red[tid >> 5] = sm;
    __syncthreads();
    if (tid == 0) {
        float s = 0.f;
#pragma unroll
        for (int i = 0; i < 8; i++) s += red[i];
        int tgt = x[b * Ln + mask_idx[b]];
        g_logp[b] = g_ip[b * Mn + tgt] - maxv - logf(s);
    }
}

__global__ void k_final(float* __restrict__ out_loss) {
    float s = 0.f;
#pragma unroll
    for (int b = 0; b < Bn; b++) s += g_logp[b];
    if (out_loss) *out_loss = -s * (1.0f / Bn);
}

// ---------------- host ----------------
extern "C" void kernel_launch(void* const* d_in, const int* in_sizes, int n_in,
                              void* d_out, int out_size) {
    const int* x = nullptr;
    const int* mask_idx = nullptr;
    const float* emb = nullptr;
    const float* pos = nullptr;
    for (int i = 0; i < n_in; i++) {
        switch (in_sizes[i]) {
            case Bn * Ln:        x = (const int*)d_in[i]; break;
            case Bn:             mask_idx = (const int*)d_in[i]; break;
            case (Mn + 1) * Dn:  emb = (const float*)d_in[i]; break;
            case Ln * Dn:        pos = (const float*)d_in[i]; break;
            default: break;
        }
    }

    float* out = (float*)d_out;
    float* lossp;
    float* selp;
    if (out_size == 1 + Bn * Dn) { lossp = out; selp = out + 1; }
    else if (out_size == Bn * Dn) { lossp = nullptr; selp = out; }
    else if (out_size == 1) { lossp = out; selp = nullptr; }
    else { lossp = out; selp = (out_size > 1) ? out + 1 : nullptr; }

    // K1: norms
    {
        int rows = Mn + 1;
        int blocks = (rows * 32 + 255) / 256;
        k_norm<<<blocks, 256>>>(emb, rows, 0);
        blocks = (Ln * 32 + 255) / 256;
        k_norm<<<blocks, 256>>>(pos, Ln, 1);
    }
    // K2: logits
    {
        dim3 g(Ln / 8, Bn);
        k_logits<<<g, 256>>>(emb, pos, x, mask_idx);
    }
    // K3: softmax
    k_softmax<<<Bn, 256>>>();
    // K4: weighted sum partials
    {
        dim3 g(16, Bn);
        k_wsum<<<g, 512>>>(emb, x, mask_idx);
    }
    // K5: reduce -> sel_output
    k_reduce_sel<<<Bn, 512>>>(selp);
    // K6: vocab inner products
    k_ip<<<Mn / 32, 128>>>(emb);
    // K7: log-softmax per batch
    k_lsm<<<Bn, 256>>>(x, mask_idx);
    // K8: final loss
    k_final<<<1, 1>>>(lossp);
}